// round 6
// baseline (speedup 1.0000x reference)
#include <cuda_runtime.h>
#include <cuda_bf16.h>
#include <math.h>

// Problem dims
#define BB   64
#define N1   1152
#define PP   8
#define N2   128
#define DD   16
#define NDD  (N2 * DD)          // 2048

#define I_B  64                 // i's per block
#define BG   8                  // b's per block
#define NBI  (N1 / I_B)         // 18
#define NBB  (BB / BG)          // 8
#define NT   512                // 16 warps

typedef unsigned long long ull;

// Scratch (no allocations allowed -> device globals)
__device__ float  g_partial[NBI * BB * NDD];     // 9.44 MB per-(iblock,b) partials
__device__ float  g_v0[BB * NDD];                // squashed v after iteration 0
__device__ float4 g_W2[(size_t)N1 * 4096];       // 75.5 MB repacked W (d-pair layout)

// ---------------- f32x2 helpers (FFMA2: 2x fp32 throughput on sm_103a) ------
__device__ __forceinline__ ull d_fma2(ull a, ull b, ull c) {
    ull r; asm("fma.rn.f32x2 %0, %1, %2, %3;" : "=l"(r) : "l"(a), "l"(b), "l"(c)); return r;
}
__device__ __forceinline__ ull d_mul2(ull a, ull b) {
    ull r; asm("mul.rn.f32x2 %0, %1, %2;" : "=l"(r) : "l"(a), "l"(b)); return r;
}
__device__ __forceinline__ ull d_dup(float x) {
    ull r; unsigned u = __float_as_uint(x);
    asm("mov.b64 %0, {%1, %2};" : "=l"(r) : "r"(u), "r"(u)); return r;
}
__device__ __forceinline__ ull d_pack(float lo, float hi) {
    ull r; unsigned a = __float_as_uint(lo), b = __float_as_uint(hi);
    asm("mov.b64 %0, {%1, %2};" : "=l"(r) : "r"(a), "r"(b)); return r;
}
__device__ __forceinline__ float d_hadd(ull a) {
    unsigned lo, hi; asm("mov.b64 {%0, %1}, %2;" : "=r"(lo), "=r"(hi) : "l"(a));
    return __uint_as_float(lo) + __uint_as_float(hi);
}
__device__ __forceinline__ void d_unpack(ull a, float& lo, float& hi) {
    unsigned x, y; asm("mov.b64 {%0, %1}, %2;" : "=r"(x), "=r"(y) : "l"(a));
    lo = __uint_as_float(x); hi = __uint_as_float(y);
}

// ---------------------------------------------------------------------------
// Repack W: dst float4[idx], idx = i*4096 + w*256 + p*32 + l holds
//   { W[i, n, dq+0, p], W[i, n, dq+1, p], W[i, n, dq+2, p], W[i, n, dq+3, p] }
// with n = 8w + (l>>2), dq = (l&3)*4.  Main pass loads wv[p] = base[p*32+l]
// (perfectly coalesced) and each float4 is 2 ready-made d-pairs for FFMA2.
// Block = one (i,w): its 8 warps are the 8 p's -> same sectors, L1 merges.
// ---------------------------------------------------------------------------
__global__ __launch_bounds__(256) void repack_W(const float* __restrict__ W)
{
    const size_t idx = (size_t)blockIdx.x * 256 + threadIdx.x;  // float4 index
    const int l  = (int)(idx & 31);
    const int p  = (int)((idx >> 5) & 7);
    const int w  = (int)((idx >> 8) & 15);
    const size_t i = idx >> 12;
    const int n  = w * 8 + (l >> 2);
    const int dq = (l & 3) * 4;
    const float* src = W + i * 16384 + n * 128 + p;
    float4 v;
    v.x = src[(dq + 0) * 8]; v.y = src[(dq + 1) * 8];
    v.z = src[(dq + 2) * 8]; v.w = src[(dq + 3) * 8];
    g_W2[idx] = v;
}

// ---------------------------------------------------------------------------
// One kernel, two modes. Mapping: warp w owns n in [8w,8w+8); lane l:
// n = 8w + (l>>2), d-pair-quad dq = (l&3)*4. pred held as 2 f32x2 d-pairs.
// ---------------------------------------------------------------------------
template<bool ROUTE>
__global__ __launch_bounds__(NT) void caps_pass(
    const float* __restrict__ x, const float* __restrict__ v0in)
{
    extern __shared__ float sm[];
    float* x_sh = sm;                                   // BG*I_B*PP = 4096 floats
    float* v0s  = sm + 4096;                            // ROUTE: BG*NDD = 16384
    float* red  = sm + 4096 + (ROUTE ? 16384 : 0);      // ROUTE: 2*16*9 = 288

    const int tid = threadIdx.x;
    const int w   = tid >> 5;
    const int l   = tid & 31;
    const int n   = w * 8 + (l >> 2);
    const int dq  = (l & 3) * 4;
    const int ib0 = blockIdx.x * I_B;
    const int b0  = blockIdx.y * BG;

    for (int t = tid; t < BG * I_B * PP; t += NT) {
        const int bb  = t >> 9;
        const int rem = t & 511;
        x_sh[t] = x[(size_t)(b0 + bb) * (N1 * PP) + (size_t)ib0 * PP + rem];
    }
    if (ROUTE) {
        for (int t = tid; t < BG * NDD; t += NT) {
            const int bb  = t >> 11;
            const int rem = t & 2047;
            v0s[t] = v0in[(size_t)(b0 + bb) * NDD + rem];
        }
    }
    __syncthreads();

    ull sacc2[BG][2];
#pragma unroll
    for (int bb = 0; bb < BG; ++bb) { sacc2[bb][0] = 0ull; sacc2[bb][1] = 0ull; }

    int buf = 0;
#pragma unroll 1
    for (int ii = 0; ii < I_B; ++ii) {
        const ulonglong2* Wp = (const ulonglong2*)(g_W2
            + (((size_t)(ib0 + ii)) << 12) + (w << 8));
        ulonglong2 wv[8];
#pragma unroll
        for (int p = 0; p < 8; ++p) wv[p] = Wp[p * 32 + l];   // 8x LDG.128, MLP=8

        if (!ROUTE) {
#pragma unroll
            for (int bb = 0; bb < BG; ++bb) {
                const float4 xa = *(const float4*)&x_sh[bb * 512 + ii * PP];
                const float4 xb = *(const float4*)&x_sh[bb * 512 + ii * PP + 4];
                const ull x0 = d_dup(xa.x), x1 = d_dup(xa.y), x2 = d_dup(xa.z), x3 = d_dup(xa.w);
                const ull x4 = d_dup(xb.x), x5 = d_dup(xb.y), x6 = d_dup(xb.z), x7 = d_dup(xb.w);
                ull a = sacc2[bb][0], b = sacc2[bb][1];
                a = d_fma2(x0, wv[0].x, a); b = d_fma2(x0, wv[0].y, b);
                a = d_fma2(x1, wv[1].x, a); b = d_fma2(x1, wv[1].y, b);
                a = d_fma2(x2, wv[2].x, a); b = d_fma2(x2, wv[2].y, b);
                a = d_fma2(x3, wv[3].x, a); b = d_fma2(x3, wv[3].y, b);
                a = d_fma2(x4, wv[4].x, a); b = d_fma2(x4, wv[4].y, b);
                a = d_fma2(x5, wv[5].x, a); b = d_fma2(x5, wv[5].y, b);
                a = d_fma2(x6, wv[6].x, a); b = d_fma2(x6, wv[6].y, b);
                a = d_fma2(x7, wv[7].x, a); b = d_fma2(x7, wv[7].y, b);
                sacc2[bb][0] = a; sacc2[bb][1] = b;
            }
        } else {
            ull pr2[BG][2];
#pragma unroll
            for (int bb = 0; bb < BG; ++bb) {
                const float4 xa = *(const float4*)&x_sh[bb * 512 + ii * PP];
                const float4 xb = *(const float4*)&x_sh[bb * 512 + ii * PP + 4];
                const ull x0 = d_dup(xa.x), x1 = d_dup(xa.y), x2 = d_dup(xa.z), x3 = d_dup(xa.w);
                const ull x4 = d_dup(xb.x), x5 = d_dup(xb.y), x6 = d_dup(xb.z), x7 = d_dup(xb.w);
                ull a = d_mul2(x0, wv[0].x);
                ull b = d_mul2(x0, wv[0].y);
                a = d_fma2(x1, wv[1].x, a); b = d_fma2(x1, wv[1].y, b);
                a = d_fma2(x2, wv[2].x, a); b = d_fma2(x2, wv[2].y, b);
                a = d_fma2(x3, wv[3].x, a); b = d_fma2(x3, wv[3].y, b);
                a = d_fma2(x4, wv[4].x, a); b = d_fma2(x4, wv[4].y, b);
                a = d_fma2(x5, wv[5].x, a); b = d_fma2(x5, wv[5].y, b);
                a = d_fma2(x6, wv[6].x, a); b = d_fma2(x6, wv[6].y, b);
                a = d_fma2(x7, wv[7].x, a); b = d_fma2(x7, wv[7].y, b);
                pr2[bb][0] = a; pr2[bb][1] = b;
            }

            // agreement + exp + warp partial sum; fold e into pred
#pragma unroll
            for (int bb = 0; bb < BG; ++bb) {
                const float4 vv = *(const float4*)&v0s[bb * NDD + n * DD + dq];
                const ull v01 = d_pack(vv.x, vv.y);
                const ull v23 = d_pack(vv.z, vv.w);
                const ull t = d_fma2(pr2[bb][0], v01, d_mul2(pr2[bb][1], v23));
                float r = d_hadd(t);
                r += __shfl_xor_sync(0xFFFFFFFFu, r, 1);
                r += __shfl_xor_sync(0xFFFFFFFFu, r, 2);      // full 16-d dot
                const float e = __expf(r);
                float S = e;
                S += __shfl_xor_sync(0xFFFFFFFFu, S, 4);
                S += __shfl_xor_sync(0xFFFFFFFFu, S, 8);
                S += __shfl_xor_sync(0xFFFFFFFFu, S, 16);     // sum over warp's 8 n
                if (l == 0) red[(buf * 16 + w) * 9 + bb] = S;
                const ull ed = d_dup(e);
                pr2[bb][0] = d_mul2(pr2[bb][0], ed);
                pr2[bb][1] = d_mul2(pr2[bb][1], ed);
            }
            __syncthreads();                                  // one barrier per ii

            // block combine: 16 warp sums per b (stride-9 pad, conflict-free)
#pragma unroll
            for (int bb = 0; bb < BG; ++bb) {
                float sv = red[(buf * 16 + (l & 15)) * 9 + bb];
                sv += __shfl_xor_sync(0xFFFFFFFFu, sv, 1);
                sv += __shfl_xor_sync(0xFFFFFFFFu, sv, 2);
                sv += __shfl_xor_sync(0xFFFFFFFFu, sv, 4);
                sv += __shfl_xor_sync(0xFFFFFFFFu, sv, 8);    // = sum over all 128 n
                const ull cd = d_dup(1.0f / sv);              // FIXED (was 4.0f/sv)
                sacc2[bb][0] = d_fma2(cd, pr2[bb][0], sacc2[bb][0]);
                sacc2[bb][1] = d_fma2(cd, pr2[bb][1], sacc2[bb][1]);
            }
            buf ^= 1;
        }
    }

    // write per-(iblock,b) partials
#pragma unroll
    for (int bb = 0; bb < BG; ++bb) {
        float4 o;
        d_unpack(sacc2[bb][0], o.x, o.y);
        d_unpack(sacc2[bb][1], o.z, o.w);
        float* gp = g_partial + ((size_t)blockIdx.x * BB + (b0 + bb)) * NDD + n * DD + dq;
        *(float4*)gp = o;
    }
}

// ---------------------------------------------------------------------------
// Reduce the NBI partials, scale, squash, write out.
// 4 lanes per (b,n) row; quad shuffles for the norm. Unrolled for MLP.
// ---------------------------------------------------------------------------
__global__ __launch_bounds__(256) void reduce_squash_kernel(float* __restrict__ out, float scale)
{
    const int t = blockIdx.x * 256 + threadIdx.x;
    const int r = t >> 2;
    const int quad = t & 3;

    float4 s = make_float4(0.f, 0.f, 0.f, 0.f);
#pragma unroll 3
    for (int blk = 0; blk < NBI; ++blk) {
        const float4 a = *(const float4*)(g_partial
            + ((size_t)blk * (BB * N2) + r) * DD + quad * 4);
        s.x += a.x; s.y += a.y; s.z += a.z; s.w += a.w;
    }
    s.x *= scale; s.y *= scale; s.z *= scale; s.w *= scale;

    float sq = s.x * s.x + s.y * s.y + s.z * s.z + s.w * s.w;
    sq += __shfl_xor_sync(0xFFFFFFFFu, sq, 1);
    sq += __shfl_xor_sync(0xFFFFFFFFu, sq, 2);

    const float norm = sqrtf(sq + 1.1920929e-7f);
    const float f = sq / ((1.0f + sq) * norm);
    *(float4*)(out + (size_t)r * DD + quad * 4) =
        make_float4(f * s.x, f * s.y, f * s.z, f * s.w);
}

// ---------------------------------------------------------------------------
extern "C" void kernel_launch(void* const* d_in, const int* in_sizes, int n_in,
                              void* d_out, int out_size)
{
    const float* x = (const float*)d_in[0];
    const float* W = (const float*)d_in[1];
    if (n_in >= 2 && in_sizes[0] > in_sizes[1]) {   // safety: x is the smaller tensor
        const float* t = x; x = W; W = t;
    }
    float* out = (float*)d_out;

    float* d_v0;
    cudaGetSymbolAddress((void**)&d_v0, g_v0);

    const int smem0 = 4096 * 4;                      // pass 0: x tile only
    const int smem1 = (4096 + 16384 + 288) * 4;      // routing: + v0 + red = 83 KB
    cudaFuncSetAttribute(caps_pass<true>,
                         cudaFuncAttributeMaxDynamicSharedMemorySize, smem1);

    // repack W into d-pair warp-coalesced layout
    repack_W<<<(int)(((size_t)N1 * 4096) / 256), 256>>>(W);

    dim3 grid(NBI, NBB);

    // iteration 0: uniform coupling -> s0 = (1/128) * sum_i pred
    caps_pass<false><<<grid, NT, smem0>>>(x, nullptr);
    reduce_squash_kernel<<<128, 256>>>(d_v0, 1.0f / 128.0f);

    // iteration 1: softmax(agreement) routing, final squash -> output
    caps_pass<true><<<grid, NT, smem1>>>(x, d_v0);
    reduce_squash_kernel<<<128, 256>>>(out, 1.0f);
}

// round 7
// speedup vs baseline: 1.3084x; 1.3084x over previous
#include <cuda_runtime.h>
#include <cuda_bf16.h>
#include <math.h>

// Problem dims
#define BB   64
#define N1   1152
#define PP   8
#define N2   128
#define DD   16
#define NDD  (N2 * DD)          // 2048

#define I_B  64                 // i's per block
#define BG   4                  // b's per block
#define NBI  (N1 / I_B)         // 18
#define NBB  (BB / BG)          // 16
#define NT   256                // 8 warps; each warp covers n and n+64

typedef unsigned long long ull;

// Scratch (no allocations allowed -> device globals)
__device__ float  g_partial[NBI * BB * NDD];     // 9.44 MB per-(iblock,b) partials
__device__ float  g_v0[BB * NDD];                // squashed v after iteration 0
__device__ float4 g_W2[(size_t)N1 * 4096];       // 75.5 MB repacked W (d-pair layout)

// ---------------- f32x2 helpers (2x fp32 throughput on sm_103a) -------------
__device__ __forceinline__ ull d_fma2(ull a, ull b, ull c) {
    ull r; asm("fma.rn.f32x2 %0, %1, %2, %3;" : "=l"(r) : "l"(a), "l"(b), "l"(c)); return r;
}
__device__ __forceinline__ ull d_mul2(ull a, ull b) {
    ull r; asm("mul.rn.f32x2 %0, %1, %2;" : "=l"(r) : "l"(a), "l"(b)); return r;
}
__device__ __forceinline__ ull d_add2(ull a, ull b) {
    ull r; asm("add.rn.f32x2 %0, %1, %2;" : "=l"(r) : "l"(a), "l"(b)); return r;
}
__device__ __forceinline__ ull d_dup(float x) {
    ull r; unsigned u = __float_as_uint(x);
    asm("mov.b64 %0, {%1, %2};" : "=l"(r) : "r"(u), "r"(u)); return r;
}
__device__ __forceinline__ ull d_pack(float lo, float hi) {
    ull r; unsigned a = __float_as_uint(lo), b = __float_as_uint(hi);
    asm("mov.b64 %0, {%1, %2};" : "=l"(r) : "r"(a), "r"(b)); return r;
}
__device__ __forceinline__ float d_hadd(ull a) {
    unsigned lo, hi; asm("mov.b64 {%0, %1}, %2;" : "=r"(lo), "=r"(hi) : "l"(a));
    return __uint_as_float(lo) + __uint_as_float(hi);
}
__device__ __forceinline__ void d_unpack(ull a, float& lo, float& hi) {
    unsigned x, y; asm("mov.b64 {%0, %1}, %2;" : "=r"(x), "=r"(y) : "l"(a));
    lo = __uint_as_float(x); hi = __uint_as_float(y);
}

// ---------------------------------------------------------------------------
// Repack W (unchanged layout): float4 idx = i*4096 + ow*256 + p*32 + l holds
//   { W[i,n,dq+0,p], W[i,n,dq+1,p], W[i,n,dq+2,p], W[i,n,dq+3,p] }
// with n = 8*ow + (l>>2), dq = (l&3)*4, ow in [0,16).
// Main pass (8 warps) uses ow = w + 8*g for n-group g in {0,1}.
// ---------------------------------------------------------------------------
__global__ __launch_bounds__(256) void repack_W(const float* __restrict__ W)
{
    const size_t idx = (size_t)blockIdx.x * 256 + threadIdx.x;
    const int l  = (int)(idx & 31);
    const int p  = (int)((idx >> 5) & 7);
    const int ow = (int)((idx >> 8) & 15);
    const size_t i = idx >> 12;
    const int n  = ow * 8 + (l >> 2);
    const int dq = (l & 3) * 4;
    const float* src = W + i * 16384 + n * 128 + p;
    float4 v;
    v.x = src[(dq + 0) * 8]; v.y = src[(dq + 1) * 8];
    v.z = src[(dq + 2) * 8]; v.w = src[(dq + 3) * 8];
    g_W2[idx] = v;
}

// ---------------------------------------------------------------------------
// One kernel, two modes. 256 threads, 2 CTAs/SM.
// Warp w owns n-groups {8w..8w+8} and {64+8w..64+8w+8}; lane l:
// n = 8w + (l>>2) (+64g), d-quad dq = (l&3)*4, pred = 2 f32x2 d-pairs.
// Softmax combine: warp partial sums (float2 over 2 n-groups) -> smem ->
// one 256-thread barrier per ii -> broadcast LDS + f32x2 adds (no shfl chain).
// ---------------------------------------------------------------------------
template<bool ROUTE>
__global__ __launch_bounds__(NT, 2) void caps_pass(
    const float* __restrict__ x, const float* __restrict__ v0in)
{
    extern __shared__ float sm[];
    ull*   x2  = (ull*)sm;                              // 2048 ull = 16 KB (dup'd x)
    float* v0s = sm + 4096;                             // ROUTE: 8192 floats = 32 KB
    float2* red = (float2*)(sm + 4096 + (ROUTE ? 8192 : 0)); // 2*8*4 float2 = 256 B

    const int tid = threadIdx.x;
    const int w   = tid >> 5;
    const int l   = tid & 31;
    const int nb  = w * 8 + (l >> 2);                   // n for g=0 (g=1: +64)
    const int dq  = (l & 3) * 4;
    const int ib0 = blockIdx.x * I_B;
    const int b0  = blockIdx.y * BG;

    // stage x duplicated as f32x2: x2[bb*512 + ii*8 + p] = (x, x)
    for (int t = tid; t < BG * I_B * PP; t += NT) {
        const int bb  = t >> 9;
        const int rem = t & 511;
        x2[t] = d_dup(x[(size_t)(b0 + bb) * (N1 * PP) + (size_t)ib0 * PP + rem]);
    }
    if (ROUTE) {
        for (int t = tid; t < BG * NDD; t += NT) {
            const int bb  = t >> 11;
            const int rem = t & 2047;
            v0s[t] = v0in[(size_t)(b0 + bb) * NDD + rem];
        }
    }
    __syncthreads();

    ull sacc[2][BG][2];
#pragma unroll
    for (int g = 0; g < 2; ++g)
#pragma unroll
        for (int bb = 0; bb < BG; ++bb) { sacc[g][bb][0] = 0ull; sacc[g][bb][1] = 0ull; }

    int buf = 0;
#pragma unroll 1
    for (int ii = 0; ii < I_B; ++ii) {
        if (!ROUTE) {
#pragma unroll
            for (int g = 0; g < 2; ++g) {
                const ulonglong2* Wp = (const ulonglong2*)(g_W2
                    + (((size_t)(ib0 + ii)) << 12) + ((w + 8 * g) << 8));
                ulonglong2 wv[8];
#pragma unroll
                for (int p = 0; p < 8; ++p) wv[p] = Wp[p * 32 + l];
#pragma unroll
                for (int bb = 0; bb < BG; ++bb) {
                    const ull* xq = x2 + bb * 512 + ii * 8;
                    ull a = sacc[g][bb][0], b = sacc[g][bb][1];
#pragma unroll
                    for (int p = 0; p < 8; ++p) {
                        const ull xp = xq[p];                 // broadcast LDS.64
                        a = d_fma2(xp, wv[p].x, a);
                        b = d_fma2(xp, wv[p].y, b);
                    }
                    sacc[g][bb][0] = a; sacc[g][bb][1] = b;
                }
            }
        } else {
            ull pr[2][BG][2];
            float S[2][BG];
#pragma unroll
            for (int g = 0; g < 2; ++g) {
                const ulonglong2* Wp = (const ulonglong2*)(g_W2
                    + (((size_t)(ib0 + ii)) << 12) + ((w + 8 * g) << 8));
                ulonglong2 wv[8];
#pragma unroll
                for (int p = 0; p < 8; ++p) wv[p] = Wp[p * 32 + l];
#pragma unroll
                for (int bb = 0; bb < BG; ++bb) {
                    const ull* xq = x2 + bb * 512 + ii * 8;
                    ull a = d_mul2(xq[0], wv[0].x);
                    ull b = d_mul2(xq[0], wv[0].y);
#pragma unroll
                    for (int p = 1; p < 8; ++p) {
                        const ull xp = xq[p];
                        a = d_fma2(xp, wv[p].x, a);
                        b = d_fma2(xp, wv[p].y, b);
                    }
                    pr[g][bb][0] = a; pr[g][bb][1] = b;
                }
                // agreement + exp + warp partial sum over this group's 8 n
#pragma unroll
                for (int bb = 0; bb < BG; ++bb) {
                    const float4 vv = *(const float4*)&v0s[bb * NDD + (nb + 64 * g) * DD + dq];
                    const ull t = d_fma2(pr[g][bb][0], d_pack(vv.x, vv.y),
                                         d_mul2(pr[g][bb][1], d_pack(vv.z, vv.w)));
                    float r = d_hadd(t);
                    r += __shfl_xor_sync(0xFFFFFFFFu, r, 1);
                    r += __shfl_xor_sync(0xFFFFFFFFu, r, 2);      // full 16-d dot
                    const float e = __expf(r);                    // |r| small; no max-sub
                    float Sg = e;
                    Sg += __shfl_xor_sync(0xFFFFFFFFu, Sg, 4);
                    Sg += __shfl_xor_sync(0xFFFFFFFFu, Sg, 8);
                    Sg += __shfl_xor_sync(0xFFFFFFFFu, Sg, 16);   // sum of 8 n
                    S[g][bb] = Sg;
                    const ull ed = d_dup(e);
                    pr[g][bb][0] = d_mul2(pr[g][bb][0], ed);      // fold e into pred
                    pr[g][bb][1] = d_mul2(pr[g][bb][1], ed);
                }
            }
            if (l == 0) {
#pragma unroll
                for (int bb = 0; bb < BG; ++bb)
                    red[(buf * 8 + w) * 4 + bb] = make_float2(S[0][bb], S[1][bb]);
            }
            __syncthreads();                                      // one barrier per ii

            // Z[bb] = sum over 8 warps x 2 groups, via broadcast LDS + ADD2
            ull z[BG] = {0ull, 0ull, 0ull, 0ull};
#pragma unroll
            for (int k = 0; k < 8; ++k) {
                const ulonglong2* rp = (const ulonglong2*)&red[(buf * 8 + k) * 4];
                const ulonglong2 a = rp[0], b = rp[1];            // bb 0..3 (S0,S1) pairs
                z[0] = d_add2(z[0], a.x); z[1] = d_add2(z[1], a.y);
                z[2] = d_add2(z[2], b.x); z[3] = d_add2(z[3], b.y);
            }
#pragma unroll
            for (int bb = 0; bb < BG; ++bb) {
                const float Z  = d_hadd(z[bb]);                   // sum over all 128 n
                const ull  cd  = d_dup(__fdividef(1.0f, Z));
                sacc[0][bb][0] = d_fma2(cd, pr[0][bb][0], sacc[0][bb][0]);
                sacc[0][bb][1] = d_fma2(cd, pr[0][bb][1], sacc[0][bb][1]);
                sacc[1][bb][0] = d_fma2(cd, pr[1][bb][0], sacc[1][bb][0]);
                sacc[1][bb][1] = d_fma2(cd, pr[1][bb][1], sacc[1][bb][1]);
            }
            buf ^= 1;                                             // WAR-safe double buffer
        }
    }

    // write per-(iblock,b) partials
#pragma unroll
    for (int g = 0; g < 2; ++g)
#pragma unroll
        for (int bb = 0; bb < BG; ++bb) {
            float4 o;
            d_unpack(sacc[g][bb][0], o.x, o.y);
            d_unpack(sacc[g][bb][1], o.z, o.w);
            float* gp = g_partial + ((size_t)blockIdx.x * BB + (b0 + bb)) * NDD
                      + (nb + 64 * g) * DD + dq;
            *(float4*)gp = o;
        }
}

// ---------------------------------------------------------------------------
// Reduce the NBI partials, scale, squash, write out.
// 4 lanes per (b,n) row; quad shuffles for the norm.
// ---------------------------------------------------------------------------
__global__ __launch_bounds__(256) void reduce_squash_kernel(float* __restrict__ out, float scale)
{
    const int t = blockIdx.x * 256 + threadIdx.x;
    const int r = t >> 2;
    const int quad = t & 3;

    float4 s = make_float4(0.f, 0.f, 0.f, 0.f);
#pragma unroll 3
    for (int blk = 0; blk < NBI; ++blk) {
        const float4 a = *(const float4*)(g_partial
            + ((size_t)blk * (BB * N2) + r) * DD + quad * 4);
        s.x += a.x; s.y += a.y; s.z += a.z; s.w += a.w;
    }
    s.x *= scale; s.y *= scale; s.z *= scale; s.w *= scale;

    float sq = s.x * s.x + s.y * s.y + s.z * s.z + s.w * s.w;
    sq += __shfl_xor_sync(0xFFFFFFFFu, sq, 1);
    sq += __shfl_xor_sync(0xFFFFFFFFu, sq, 2);

    const float norm = sqrtf(sq + 1.1920929e-7f);
    const float f = sq / ((1.0f + sq) * norm);
    *(float4*)(out + (size_t)r * DD + quad * 4) =
        make_float4(f * s.x, f * s.y, f * s.z, f * s.w);
}

// ---------------------------------------------------------------------------
extern "C" void kernel_launch(void* const* d_in, const int* in_sizes, int n_in,
                              void* d_out, int out_size)
{
    const float* x = (const float*)d_in[0];
    const float* W = (const float*)d_in[1];
    if (n_in >= 2 && in_sizes[0] > in_sizes[1]) {   // safety: x is the smaller tensor
        const float* t = x; x = W; W = t;
    }
    float* out = (float*)d_out;

    float* d_v0;
    cudaGetSymbolAddress((void**)&d_v0, g_v0);

    const int smem0 = 4096 * 4;                              // x tile only (16 KB)
    const int smem1 = (4096 + 8192) * 4 + 2 * 8 * 4 * 8;     // + v0 + red = 49.4 KB
    cudaFuncSetAttribute(caps_pass<true>,
                         cudaFuncAttributeMaxDynamicSharedMemorySize, smem1);

    // repack W into d-pair warp-coalesced layout
    repack_W<<<(int)(((size_t)N1 * 4096) / 256), 256>>>(W);

    dim3 grid(NBI, NBB);    // 18 x 16 = 288 blocks = one wave at 2 CTA/SM

    // iteration 0: uniform coupling -> s0 = (1/128) * sum_i pred
    caps_pass<false><<<grid, NT, smem0>>>(x, nullptr);
    reduce_squash_kernel<<<128, 256>>>(d_v0, 1.0f / 128.0f);

    // iteration 1: softmax(agreement) routing, final squash -> output
    caps_pass<true><<<grid, NT, smem1>>>(x, d_v0);
    reduce_squash_kernel<<<128, 256>>>(out, 1.0f);
}